// round 9
// baseline (speedup 1.0000x reference)
#include <cuda_runtime.h>

// SpinorBilinears: psi [B=8, N=65536, S=4] f32, gamma [C=8, 4, 4] f32.
// Outputs flat: K0 [BN] | K1 [BN,8,8] | K2 [BN,8,8]
//   u_c = gamma_c^T (0.5 p),  v_c = gamma_c p     (0.5 folded into u)
//   K1[c][d] = u_c.v_d - u_d.v_c,   K2[c][d] = u_c.v_d + u_d.v_c
//
// One thread per token. gamma read via warp-uniform __ldg broadcasts (no
// extra graph nodes). Warp-private 8KB swizzled staging + __syncwarp only.
// __launch_bounds__(128,6) caps regs at ~85 -> 6 blocks/SM (24 warps).

#define TPB 128

__device__ __forceinline__ float dot4f(float4 a, float4 b) {
    return fmaf(a.x, b.x, fmaf(a.y, b.y, fmaf(a.z, b.z, a.w * b.w)));
}

__device__ __forceinline__ int swz(int e4, int l) {     // float4-index swizzle
    return (e4 & 8) | ((e4 & 7) ^ (l & 7));
}

__global__ __launch_bounds__(TPB, 6) void spinor_main_kernel(
    const float4* __restrict__ psi4,
    const float4* __restrict__ gamma4,
    float* __restrict__ out,
    int BN)
{
    __shared__ float4 stage4[4][512];    // 8 KB per warp

    const int tid  = threadIdx.x;
    const int warp = tid >> 5;
    const int l    = tid & 31;
    const int t    = blockIdx.x * TPB + tid;    // token (grid exact)

    const float4 p = psi4[t];

    // K0 (coalesced STG.32)
    out[t] = dot4f(p, p);

    // u_c = gamma_c^T (0.5p) ; v_c = gamma_c p  (gamma: warp-uniform broadcasts)
    const float4 ph = make_float4(0.5f * p.x, 0.5f * p.y, 0.5f * p.z, 0.5f * p.w);
    float4 u[8], v[8];
#pragma unroll
    for (int c = 0; c < 8; c++) {
        const float4 r0 = __ldg(gamma4 + c * 4 + 0);
        const float4 r1 = __ldg(gamma4 + c * 4 + 1);
        const float4 r2 = __ldg(gamma4 + c * 4 + 2);
        const float4 r3 = __ldg(gamma4 + c * 4 + 3);
        v[c].x = dot4f(r0, p);
        v[c].y = dot4f(r1, p);
        v[c].z = dot4f(r2, p);
        v[c].w = dot4f(r3, p);
        u[c].x = fmaf(r0.x, ph.x, fmaf(r1.x, ph.y, fmaf(r2.x, ph.z, r3.x * ph.w)));
        u[c].y = fmaf(r0.y, ph.x, fmaf(r1.y, ph.y, fmaf(r2.y, ph.z, r3.y * ph.w)));
        u[c].z = fmaf(r0.z, ph.x, fmaf(r1.z, ph.y, fmaf(r2.z, ph.z, r3.z * ph.w)));
        u[c].w = fmaf(r0.w, ph.x, fmaf(r1.w, ph.y, fmaf(r2.w, ph.z, r3.w * ph.w)));
    }

    const size_t bn = (size_t)BN;
    const int    t0 = blockIdx.x * TPB + warp * 32;   // warp's first token
    float4* __restrict__ k1dst = reinterpret_cast<float4*>(out + bn) + (size_t)t0 * 16;
    float4* __restrict__ k2dst = reinterpret_cast<float4*>(out + bn + bn * 64) + (size_t)t0 * 16;

    // ================= K1 =================
#pragma unroll
    for (int c = 0; c < 8; c++) {
#pragma unroll
        for (int d4 = 0; d4 < 2; d4++) {
            const int d = d4 * 4;
            float4 r;
            r.x = dot4f(u[c], v[d + 0]) - dot4f(u[d + 0], v[c]);
            r.y = dot4f(u[c], v[d + 1]) - dot4f(u[d + 1], v[c]);
            r.z = dot4f(u[c], v[d + 2]) - dot4f(u[d + 2], v[c]);
            r.w = dot4f(u[c], v[d + 3]) - dot4f(u[d + 3], v[c]);
            stage4[warp][l * 16 + swz(c * 2 + d4, l)] = r;
        }
    }
    __syncwarp();
    // copy-out in two batches of 8 (keeps 8 loads in flight under the reg cap)
#pragma unroll
    for (int h = 0; h < 2; h++) {
        float4 buf[8];
#pragma unroll
        for (int j = 0; j < 8; j++) {
            const int f4  = (h * 8 + j) * 32 + l;
            buf[j] = stage4[warp][(f4 >> 4) * 16 + swz(f4 & 15, f4 >> 4)];
        }
#pragma unroll
        for (int j = 0; j < 8; j++) {
            const int f4 = (h * 8 + j) * 32 + l;
            k1dst[f4] = buf[j];
        }
    }
    __syncwarp();

    // ================= K2 =================
#pragma unroll
    for (int c = 0; c < 8; c++) {
#pragma unroll
        for (int d4 = 0; d4 < 2; d4++) {
            const int d = d4 * 4;
            float4 r;
            r.x = dot4f(u[c], v[d + 0]) + dot4f(u[d + 0], v[c]);
            r.y = dot4f(u[c], v[d + 1]) + dot4f(u[d + 1], v[c]);
            r.z = dot4f(u[c], v[d + 2]) + dot4f(u[d + 2], v[c]);
            r.w = dot4f(u[c], v[d + 3]) + dot4f(u[d + 3], v[c]);
            stage4[warp][l * 16 + swz(c * 2 + d4, l)] = r;
        }
    }
    __syncwarp();
#pragma unroll
    for (int h = 0; h < 2; h++) {
        float4 buf[8];
#pragma unroll
        for (int j = 0; j < 8; j++) {
            const int f4  = (h * 8 + j) * 32 + l;
            buf[j] = stage4[warp][(f4 >> 4) * 16 + swz(f4 & 15, f4 >> 4)];
        }
#pragma unroll
        for (int j = 0; j < 8; j++) {
            const int f4 = (h * 8 + j) * 32 + l;
            k2dst[f4] = buf[j];
        }
    }
}

extern "C" void kernel_launch(void* const* d_in, const int* in_sizes, int n_in,
                              void* d_out, int out_size) {
    const float4* psi4   = (const float4*)d_in[0];   // [B, N, 4] f32
    const float4* gamma4 = (const float4*)d_in[1];   // [8, 4, 4] f32
    float* out = (float*)d_out;

    const int BN = in_sizes[0] / 4;                  // 524288 tokens

    spinor_main_kernel<<<BN / TPB, TPB>>>(psi4, gamma4, out, BN);
}

// round 10
// speedup vs baseline: 1.3203x; 1.3203x over previous
#include <cuda_runtime.h>

// SpinorBilinears: psi [B=8, N=65536, S=4] f32, gamma [C=8, 4, 4] f32.
// Outputs flat in d_out: K0 [BN] | K1 [BN,8,8] | K2 [BN,8,8]
//   u_c = gamma_c^T p,  v_c = gamma_c p
//   K1[c][d] = 0.5*(u_c.v_d - u_d.v_c),  K2[c][d] = 0.5*(u_c.v_d + u_d.v_c)
//
// R0 structure (best measured) + __stcs streaming stores on the write-once
// output stream (evict-first in L2 -> smoother HBM write drain).

#define TPB 128

__device__ __forceinline__ float dot4(const float* a, const float* b) {
    return fmaf(a[0], b[0], fmaf(a[1], b[1], fmaf(a[2], b[2], a[3] * b[3])));
}

__global__ __launch_bounds__(TPB) void spinor_bilinears_kernel(
    const float4* __restrict__ psi4,
    const float4* __restrict__ gamma4,
    float* __restrict__ out,
    int BN)
{
    __shared__ float4 sg[32];            // gamma: 8 matrices x 4 rows, as float4
    __shared__ float  stage[TPB * 64];   // 32 KB staging for one [128 tokens x 64] matrix

    const int tid = threadIdx.x;
    if (tid < 32) sg[tid] = __ldg(gamma4 + tid);
    __syncthreads();

    const int t = blockIdx.x * TPB + tid;   // token id; grid sized exactly BN/TPB

    // ---- load spinor (16B aligned, coalesced) ----
    const float4 p4 = __ldg(psi4 + t);
    const float p[4] = {p4.x, p4.y, p4.z, p4.w};

    // ---- K0 (coalesced streaming STG.32) ----
    __stcs(out + t, dot4(p, p));

    // ---- u_c = gamma_c^T p ; v_c = gamma_c p ----
    float u[8][4], v[8][4];
#pragma unroll
    for (int c = 0; c < 8; c++) {
        const float4 r0 = sg[c * 4 + 0];
        const float4 r1 = sg[c * 4 + 1];
        const float4 r2 = sg[c * 4 + 2];
        const float4 r3 = sg[c * 4 + 3];
        v[c][0] = fmaf(r0.x, p[0], fmaf(r0.y, p[1], fmaf(r0.z, p[2], r0.w * p[3])));
        v[c][1] = fmaf(r1.x, p[0], fmaf(r1.y, p[1], fmaf(r1.z, p[2], r1.w * p[3])));
        v[c][2] = fmaf(r2.x, p[0], fmaf(r2.y, p[1], fmaf(r2.z, p[2], r2.w * p[3])));
        v[c][3] = fmaf(r3.x, p[0], fmaf(r3.y, p[1], fmaf(r3.z, p[2], r3.w * p[3])));
        u[c][0] = fmaf(r0.x, p[0], fmaf(r1.x, p[1], fmaf(r2.x, p[2], r3.x * p[3])));
        u[c][1] = fmaf(r0.y, p[0], fmaf(r1.y, p[1], fmaf(r2.y, p[2], r3.y * p[3])));
        u[c][2] = fmaf(r0.z, p[0], fmaf(r1.z, p[1], fmaf(r2.z, p[2], r3.z * p[3])));
        u[c][3] = fmaf(r0.w, p[0], fmaf(r1.w, p[1], fmaf(r2.w, p[2], r3.w * p[3])));
    }

    const size_t bn      = (size_t)BN;
    const size_t blkBase = (size_t)blockIdx.x * (size_t)(TPB * 64);
    const int    sw      = tid & 15;     // float4-granular XOR swizzle key

    // ================= K1 (antisymmetric) =================
#pragma unroll
    for (int c = 0; c < 8; c++) {
#pragma unroll
        for (int d4 = 0; d4 < 2; d4++) {
            float4 row;
            {
                const int d = d4 * 4;
                row.x = 0.5f * (dot4(u[c], v[d + 0]) - dot4(u[d + 0], v[c]));
                row.y = 0.5f * (dot4(u[c], v[d + 1]) - dot4(u[d + 1], v[c]));
                row.z = 0.5f * (dot4(u[c], v[d + 2]) - dot4(u[d + 2], v[c]));
                row.w = 0.5f * (dot4(u[c], v[d + 3]) - dot4(u[d + 3], v[c]));
            }
            const int e4 = c * 2 + d4;                              // 0..15
            *reinterpret_cast<float4*>(&stage[tid * 64 + ((e4 ^ sw) << 2)]) = row;
        }
    }
    __syncthreads();

    {
        float* __restrict__ dst = out + bn + blkBase;
#pragma unroll
        for (int it = 0; it < 16; it++) {
            const int o   = it * (TPB * 4) + tid * 4;   // float offset in block's 8192-float region
            const int tok = o >> 6;
            const int e4  = (o >> 2) & 15;
            const float4 val =
                *reinterpret_cast<const float4*>(&stage[tok * 64 + ((e4 ^ (tok & 15)) << 2)]);
            __stcs(reinterpret_cast<float4*>(&dst[o]), val);
        }
    }
    __syncthreads();

    // ================= K2 (symmetric) =================
#pragma unroll
    for (int c = 0; c < 8; c++) {
#pragma unroll
        for (int d4 = 0; d4 < 2; d4++) {
            float4 row;
            {
                const int d = d4 * 4;
                row.x = 0.5f * (dot4(u[c], v[d + 0]) + dot4(u[d + 0], v[c]));
                row.y = 0.5f * (dot4(u[c], v[d + 1]) + dot4(u[d + 1], v[c]));
                row.z = 0.5f * (dot4(u[c], v[d + 2]) + dot4(u[d + 2], v[c]));
                row.w = 0.5f * (dot4(u[c], v[d + 3]) + dot4(u[d + 3], v[c]));
            }
            const int e4 = c * 2 + d4;
            *reinterpret_cast<float4*>(&stage[tid * 64 + ((e4 ^ sw) << 2)]) = row;
        }
    }
    __syncthreads();

    {
        float* __restrict__ dst = out + bn + bn * 64 + blkBase;
#pragma unroll
        for (int it = 0; it < 16; it++) {
            const int o   = it * (TPB * 4) + tid * 4;
            const int tok = o >> 6;
            const int e4  = (o >> 2) & 15;
            const float4 val =
                *reinterpret_cast<const float4*>(&stage[tok * 64 + ((e4 ^ (tok & 15)) << 2)]);
            __stcs(reinterpret_cast<float4*>(&dst[o]), val);
        }
    }
}

extern "C" void kernel_launch(void* const* d_in, const int* in_sizes, int n_in,
                              void* d_out, int out_size) {
    const float4* psi4   = (const float4*)d_in[0];   // [B, N, 4] f32
    const float4* gamma4 = (const float4*)d_in[1];   // [8, 4, 4] f32
    float* out = (float*)d_out;

    const int BN = in_sizes[0] / 4;                  // 524288 tokens
    const int grid = BN / TPB;                       // 4096, exact

    spinor_bilinears_kernel<<<grid, TPB>>>(psi4, gamma4, out, BN);
}